// round 10
// baseline (speedup 1.0000x reference)
#include <cuda_runtime.h>
#include <cstdint>
#include <math.h>

#define TOKENS 8192
#define DMODEL 1024
#define DFF    4096
#define RANK   128
#define MT     32

// smem strides in words; ==16 (mod 32) -> conflict-free LDS.128 fragments
#define SK128 144
#define SK64  80
// smem word offsets
#define W_SA  0                    // t1 / t2 tile: 32 x 144 = 4608
#define W_SB0 4608                 // x / h staging buf 0: 32 x 80 = 2560
#define W_SB1 7168                 // x / h staging buf 1
#define SMEM_WORDS 9728            // 38912 bytes

// ---- k-permuted tf32 weight scratch (prep outputs; B-fragments LDG'd directly) ----
__device__ uint32_t g_v1[DFF * RANK];      // cfc_V          [f][perm(r)]
__device__ uint32_t g_v2[DMODEL * RANK];   // cp_V           [d][perm(r)]
__device__ uint32_t g_u1t[RANK * DMODEL];  // (cfc_U*S)^T    [r][perm(d)]
__device__ uint32_t g_u2t[RANK * DFF];     // (cp_U*S2)^T    [r][perm(f)]

__device__ __forceinline__ int pcid(int c) {           // permute low 4 bits (self-inverse)
    return (c & ~15) | ((c & 3) << 2) | ((c >> 2) & 3);
}
__device__ __forceinline__ uint32_t f2tf(float f) {
    uint32_t u; asm("cvt.rna.tf32.f32 %0, %1;" : "=r"(u) : "f"(f)); return u;
}
__device__ __forceinline__ float gelu_exact(float v) {
    return 0.5f * v * (1.f + erff(v * 0.7071067811865476f));
}
__device__ __forceinline__ void mma8(float* c,
                                     uint32_t a0, uint32_t a1, uint32_t a2, uint32_t a3,
                                     uint32_t b0, uint32_t b1) {
    asm volatile(
        "mma.sync.aligned.m16n8k8.row.col.f32.tf32.tf32.f32 "
        "{%0,%1,%2,%3}, {%4,%5,%6,%7}, {%8,%9}, {%0,%1,%2,%3};\n"
        : "+f"(c[0]), "+f"(c[1]), "+f"(c[2]), "+f"(c[3])
        : "r"(a0), "r"(a1), "r"(a2), "r"(a3), "r"(b0), "r"(b1));
}

// Warp GEMM: A (32 rows, k-permuted smem), B (k-permuted GLOBAL, L2-hot).
// NT n-tiles of 8, K = KP*16. One LDS.128 / LDG.128 feeds 2 k-steps.
template<int NT, int KP, int SA_>
__device__ __forceinline__ void gemm_gB(const uint32_t* __restrict__ A,
                                        const uint32_t* __restrict__ B, int bstride,
                                        int ncol, int qr, int qc, float (*acc)[4])
{
    #pragma unroll
    for (int kp = 0; kp < KP; kp++) {
        const int kb = kp * 16 + qc * 4;
        uint4 b[NT];
        #pragma unroll
        for (int nt = 0; nt < NT; nt++)
            b[nt] = *(const uint4*)(B + (size_t)(ncol + nt * 8 + qr) * bstride + kb);
        uint4 a0 = *(const uint4*)(A + (qr)      * SA_ + kb);
        uint4 a1 = *(const uint4*)(A + (qr + 8)  * SA_ + kb);
        uint4 a2 = *(const uint4*)(A + (qr + 16) * SA_ + kb);
        uint4 a3 = *(const uint4*)(A + (qr + 24) * SA_ + kb);
        #pragma unroll
        for (int nt = 0; nt < NT; nt++) {
            mma8(acc[nt],      a0.x, a1.x, a0.y, a1.y, b[nt].x, b[nt].y);
            mma8(acc[nt],      a0.z, a1.z, a0.w, a1.w, b[nt].z, b[nt].w);
            mma8(acc[NT + nt], a2.x, a3.x, a2.y, a3.y, b[nt].x, b[nt].y);
            mma8(acc[NT + nt], a2.z, a3.z, a2.w, a3.w, b[nt].z, b[nt].w);
        }
    }
}

// ---------------- prep: convert weights to tf32, fold S, transpose, k-permute ----------------
__global__ void prep_w_kernel(const float* __restrict__ cfc_U, const float* __restrict__ cfc_S,
                              const float* __restrict__ cfc_V,
                              const float* __restrict__ cp_U,  const float* __restrict__ cp_S,
                              const float* __restrict__ cp_V) {
    int b = blockIdx.x, t = threadIdx.x;
    if (b < 512) {                       // g_v1: [f][perm(r)]
        int i = b * 256 + t;
        int row = i >> 5, j = i & 31;
        float4 v = ((const float4*)cfc_V)[i];
        uint32_t* d = g_v1 + (size_t)row * RANK;
        int c = j * 4;
        d[pcid(c + 0)] = f2tf(v.x); d[pcid(c + 1)] = f2tf(v.y);
        d[pcid(c + 2)] = f2tf(v.z); d[pcid(c + 3)] = f2tf(v.w);
    } else if (b < 640) {                // g_v2: [d][perm(r)]
        int i = (b - 512) * 256 + t;
        int row = i >> 5, j = i & 31;
        float4 v = ((const float4*)cp_V)[i];
        uint32_t* d = g_v2 + (size_t)row * RANK;
        int c = j * 4;
        d[pcid(c + 0)] = f2tf(v.x); d[pcid(c + 1)] = f2tf(v.y);
        d[pcid(c + 2)] = f2tf(v.z); d[pcid(c + 3)] = f2tf(v.w);
    } else if (b < 1152) {               // g_u1t: [r][perm(d)] = U1[d][r]*S[r]
        int o = (b - 640) * 256 + t;
        int r = o >> 10, d = o & 1023;
        g_u1t[(size_t)r * DMODEL + pcid(d)] = f2tf(cfc_U[(size_t)d * RANK + r] * cfc_S[r]);
    } else {                             // g_u2t: [r][perm(f)] = U2[f][r]*S2[r]
        int o = (b - 1152) * 256 + t;
        int r = o >> 12, f = o & 4095;
        g_u2t[(size_t)r * DFF + pcid(f)] = f2tf(cp_U[(size_t)f * RANK + r] * cp_S[r]);
    }
}

// ---------------- main fused kernel ----------------
__global__ void __launch_bounds__(256, 2)
fused_lowrank_mlp_kernel(const float* __restrict__ x,
                         const float* __restrict__ cfc_b,
                         const float* __restrict__ cp_b,
                         float* __restrict__ out)
{
    extern __shared__ uint32_t sm[];
    uint32_t* SA = sm + W_SA;
    uint32_t* SB[2] = { sm + W_SB0, sm + W_SB1 };

    const int tid  = threadIdx.x;
    const int lane = tid & 31;
    const int warp = tid >> 5;
    const int qr   = lane >> 2;
    const int qc   = lane & 3;
    const int m0   = blockIdx.x * MT;

    // x chunk [32 tok x 64 d]: LDG float4 -> regs; STS permuted tf32 (stride 80)
    float4 xr[2];
    auto ldx = [&](int ci) {
        if (ci < 16) {
            #pragma unroll
            for (int i = 0; i < 2; i++) {
                int idx = tid + i * 256; int row = idx >> 4, j = idx & 15;
                xr[i] = *(const float4*)(x + (size_t)(m0 + row) * DMODEL + ci * 64 + j * 4);
            }
        }
    };
    auto stx = [&](uint32_t* dstb) {
        #pragma unroll
        for (int i = 0; i < 2; i++) {
            int idx = tid + i * 256; int row = idx >> 4, j = idx & 15;
            uint32_t* d = dstb + row * SK64 + (j >> 2) * 16 + (j & 3);
            d[0]  = f2tf(xr[i].x);
            d[4]  = f2tf(xr[i].y);
            d[8]  = f2tf(xr[i].z);
            d[12] = f2tf(xr[i].w);
        }
    };

    // ================= Phase 1: t1[32x128] = x @ (U1*S) =================
    float acc1[4][4];
    #pragma unroll
    for (int i = 0; i < 4; i++)
        #pragma unroll
        for (int j = 0; j < 4; j++) acc1[i][j] = 0.f;

    ldx(0); stx(SB[0]); ldx(1);
    __syncthreads();

    for (int ci = 0; ci < 16; ci++) {
        int b = ci & 1;
        gemm_gB<2, 4, SK64>(SB[b], g_u1t + ci * 64, DMODEL, warp * 16, qr, qc, acc1);
        if (ci + 1 < 16) stx(SB[1 - b]);
        ldx(ci + 2);
        __syncthreads();
    }

    // t1 epilogue -> SA (k-permuted, stride 144)
    #pragma unroll
    for (int mi = 0; mi < 2; mi++)
        #pragma unroll
        for (int nt = 0; nt < 2; nt++) {
            int c0 = warp * 16 + nt * 8 + 2 * qc;
            int r0 = mi * 16 + qr;
            float* a = acc1[mi * 2 + nt];
            SA[r0 * SK128 + pcid(c0)]           = f2tf(a[0]);
            SA[r0 * SK128 + pcid(c0 + 1)]       = f2tf(a[1]);
            SA[(r0 + 8) * SK128 + pcid(c0)]     = f2tf(a[2]);
            SA[(r0 + 8) * SK128 + pcid(c0 + 1)] = f2tf(a[3]);
        }
    __syncthreads();

    // ===== Phase 2: 64 f-chunks of 64; t2[32x128] accumulates in registers
    //       (each warp owns a 32x16 n-slice; h shared via smem -> no reduction) =====
    float t2a[4][4];
    #pragma unroll
    for (int i = 0; i < 4; i++)
        #pragma unroll
        for (int j = 0; j < 4; j++) t2a[i][j] = 0.f;

    for (int it = 0; it < 64; it++) {
        int b = it & 1;
        uint32_t* SH = SB[b];

        // GEMM2: h[32x64] = t1 @ V1c^T (K=128); warp tile 32x8
        float ha[2][4];
        #pragma unroll
        for (int i = 0; i < 2; i++)
            #pragma unroll
            for (int j = 0; j < 4; j++) ha[i][j] = 0.f;
        gemm_gB<1, 8, SK128>(SA, g_v1 + (size_t)it * 64 * RANK, RANK,
                             warp * 8, qr, qc, ha);

        // bias + exact GELU -> SH (k-permuted, stride 80)
        {
            int c0 = warp * 8 + 2 * qc;
            int fb = it * 64 + c0;
            float b0 = __ldg(cfc_b + fb), b1 = __ldg(cfc_b + fb + 1);
            #pragma unroll
            for (int mi = 0; mi < 2; mi++) {
                int r0 = mi * 16 + qr;
                float* a = ha[mi];
                SH[r0 * SK64 + pcid(c0)]           = f2tf(gelu_exact(a[0] + b0));
                SH[r0 * SK64 + pcid(c0 + 1)]       = f2tf(gelu_exact(a[1] + b1));
                SH[(r0 + 8) * SK64 + pcid(c0)]     = f2tf(gelu_exact(a[2] + b0));
                SH[(r0 + 8) * SK64 + pcid(c0 + 1)] = f2tf(gelu_exact(a[3] + b1));
            }
        }
        __syncthreads();

        // GEMM3: t2[32x128] += h @ (U2*S2)c (K=64); warp tile 32x16
        gemm_gB<2, 4, SK64>(SH, g_u2t + it * 64, DFF, warp * 16, qr, qc, t2a);
        // no second sync: next iter writes the OTHER SB buffer
    }
    __syncthreads();

    // t2 epilogue -> SA (reuse)
    #pragma unroll
    for (int mi = 0; mi < 2; mi++)
        #pragma unroll
        for (int nt = 0; nt < 2; nt++) {
            int c0 = warp * 16 + nt * 8 + 2 * qc;
            int r0 = mi * 16 + qr;
            float* a = t2a[mi * 2 + nt];
            SA[r0 * SK128 + pcid(c0)]           = f2tf(a[0]);
            SA[r0 * SK128 + pcid(c0 + 1)]       = f2tf(a[1]);
            SA[(r0 + 8) * SK128 + pcid(c0)]     = f2tf(a[2]);
            SA[(r0 + 8) * SK128 + pcid(c0 + 1)] = f2tf(a[3]);
        }
    __syncthreads();

    // ================= Phase 3: out = t2 @ V2^T + b2 (no syncs) =================
    for (int dc = 0; dc < 16; dc++) {
        float oa[2][4];
        #pragma unroll
        for (int i = 0; i < 2; i++)
            #pragma unroll
            for (int j = 0; j < 4; j++) oa[i][j] = 0.f;
        gemm_gB<1, 8, SK128>(SA, g_v2 + (size_t)dc * 64 * RANK, RANK,
                             warp * 8, qr, qc, oa);

        int c0 = warp * 8 + 2 * qc;
        int db = dc * 64 + c0;
        float b0 = __ldg(cp_b + db), b1 = __ldg(cp_b + db + 1);
        #pragma unroll
        for (int mi = 0; mi < 2; mi++) {
            int r0 = m0 + mi * 16 + qr;
            float* a = oa[mi];
            *(float2*)(out + (size_t)r0 * DMODEL + db) =
                make_float2(a[0] + b0, a[1] + b1);
            *(float2*)(out + (size_t)(r0 + 8) * DMODEL + db) =
                make_float2(a[2] + b0, a[3] + b1);
        }
    }
}

extern "C" void kernel_launch(void* const* d_in, const int* in_sizes, int n_in,
                              void* d_out, int out_size)
{
    const float* x     = (const float*)d_in[0];
    const float* cfc_U = (const float*)d_in[1];
    const float* cfc_S = (const float*)d_in[2];
    const float* cfc_V = (const float*)d_in[3];
    const float* cfc_b = (const float*)d_in[4];
    const float* cp_U  = (const float*)d_in[5];
    const float* cp_S  = (const float*)d_in[6];
    const float* cp_V  = (const float*)d_in[7];
    const float* cp_b  = (const float*)d_in[8];
    float* out = (float*)d_out;

    prep_w_kernel<<<3200, 256>>>(cfc_U, cfc_S, cfc_V, cp_U, cp_S, cp_V);

    const int smem_bytes = SMEM_WORDS * 4;   // 38912
    cudaFuncSetAttribute(fused_lowrank_mlp_kernel,
                         cudaFuncAttributeMaxDynamicSharedMemorySize, smem_bytes);
    fused_lowrank_mlp_kernel<<<TOKENS / MT, 256, smem_bytes>>>(x, cfc_b, cp_b, out);
}

// round 11
// speedup vs baseline: 1.6502x; 1.6502x over previous
#include <cuda_runtime.h>
#include <cuda_fp16.h>
#include <cstdint>
#include <math.h>

#define TOKENS 8192
#define DMODEL 1024
#define DFF    4096
#define RANK   128
#define MT     32

// word strides (1 word = half2 = 2 k-elements); all ≡16 (mod 32) -> conflict-free LDS.128
#define S64  80      // rows of 64 data words (K=128)
#define S32  48      // rows of 32 data words (K=64)

// smem word offsets
#define W_SA 0            // t1/t2 tile: 32 x 80 = 2560
#define W_SH 2560         // h tile:     32 x 48 = 1536
#define W_B0 4096         // staging buffer 0 (11264 words)
#define W_B1 15360        // staging buffer 1
#define BU_OFF 5120       // U2 part offset inside stage-2 buffer (V1 at 0)
#define BX_U1  1536       // U1 part offset inside stage-1 buffer (x at 0)
#define SMEM_WORDS 26624  // 106496 bytes -> 2 CTAs/SM

// ---- half2-packed, k-permuted weight scratch (prep outputs) ----
__device__ uint32_t g_v1h[DFF * 64];     // cfc_V    [f][word(r)]
__device__ uint32_t g_v2h[DMODEL * 64];  // cp_V     [d][word(r)]
__device__ uint32_t g_u1th[RANK * 512];  // (U1*S)^T [r][word(d)]
__device__ uint32_t g_u2th[RANK * 2048]; // (U2*S2)^T[r][word(f)]

__device__ __forceinline__ int pw(int w) {     // permute low 4 bits (self-inverse)
    return (w & ~15) | ((w & 3) << 2) | ((w >> 2) & 3);
}
__device__ __forceinline__ uint32_t pk(float lo, float hi) {
    __half2 h = __floats2half2_rn(lo, hi);
    return *(uint32_t*)&h;
}
__device__ __forceinline__ float gelu_exact(float v) {
    return 0.5f * v * (1.f + erff(v * 0.7071067811865476f));
}
__device__ __forceinline__ void mma16(float* c,
                                      uint32_t a0, uint32_t a1, uint32_t a2, uint32_t a3,
                                      uint32_t b0, uint32_t b1) {
    asm volatile(
        "mma.sync.aligned.m16n8k16.row.col.f32.f16.f16.f32 "
        "{%0,%1,%2,%3}, {%4,%5,%6,%7}, {%8,%9}, {%0,%1,%2,%3};\n"
        : "+f"(c[0]), "+f"(c[1]), "+f"(c[2]), "+f"(c[3])
        : "r"(a0), "r"(a1), "r"(a2), "r"(a3), "r"(b0), "r"(b1));
}
__device__ __forceinline__ void cpa16(uint32_t dst, const void* src) {
    asm volatile("cp.async.cg.shared.global [%0], [%1], 16;\n" :: "r"(dst), "l"(src) : "memory");
}
#define CPA_COMMIT() asm volatile("cp.async.commit_group;\n" ::: "memory")
#define CPA_WAIT1()  asm volatile("cp.async.wait_group 1;\n" ::: "memory")

// Warp GEMM: 32 A-rows (qr..qr+24), NT n-tiles of 8, K = KG*32.
// One LDS.128 per row-pair feeds TWO m16n8k16 steps. acc[2*NT][4].
template<int NT, int KG, int SA_, int SB_>
__device__ __forceinline__ void gemm16(const uint32_t* __restrict__ A,
                                       const uint32_t* __restrict__ B,
                                       int ncol, int qr, int qc, float (*acc)[4])
{
    #pragma unroll
    for (int kg = 0; kg < KG; kg++) {
        const int kb = kg * 16 + qc * 4;
        uint4 a0 = *(const uint4*)(A + (qr)      * SA_ + kb);
        uint4 a1 = *(const uint4*)(A + (qr + 8)  * SA_ + kb);
        uint4 a2 = *(const uint4*)(A + (qr + 16) * SA_ + kb);
        uint4 a3 = *(const uint4*)(A + (qr + 24) * SA_ + kb);
        uint4 b[NT];
        #pragma unroll
        for (int nt = 0; nt < NT; nt++)
            b[nt] = *(const uint4*)(B + (ncol + nt * 8 + qr) * SB_ + kb);
        #pragma unroll
        for (int nt = 0; nt < NT; nt++) {
            mma16(acc[nt],      a0.x, a1.x, a0.y, a1.y, b[nt].x, b[nt].y);
            mma16(acc[nt],      a0.z, a1.z, a0.w, a1.w, b[nt].z, b[nt].w);
            mma16(acc[NT + nt], a2.x, a3.x, a2.y, a3.y, b[nt].x, b[nt].y);
            mma16(acc[NT + nt], a2.z, a3.z, a2.w, a3.w, b[nt].z, b[nt].w);
        }
    }
}

// ---------------- prep: fp16-pack, fold S, transpose, k-permute ----------------
__global__ void prep_w_kernel(const float* __restrict__ cfc_U, const float* __restrict__ cfc_S,
                              const float* __restrict__ cfc_V,
                              const float* __restrict__ cp_U,  const float* __restrict__ cp_S,
                              const float* __restrict__ cp_V) {
    int b = blockIdx.x, t = threadIdx.x;
    if (b < 512) {                            // g_v1h: [f][word(r)]
        int i = b * 256 + t;                  // float4 over DFF x 128
        int row = i >> 5, j = i & 31;
        float4 v = ((const float4*)cfc_V)[i];
        uint32_t* d = g_v1h + (size_t)row * 64;
        d[pw(2 * j)]     = pk(v.x, v.y);
        d[pw(2 * j + 1)] = pk(v.z, v.w);
    } else if (b < 640) {                     // g_v2h: [d][word(r)]
        int i = (b - 512) * 256 + t;
        int row = i >> 5, j = i & 31;
        float4 v = ((const float4*)cp_V)[i];
        uint32_t* d = g_v2h + (size_t)row * 64;
        d[pw(2 * j)]     = pk(v.x, v.y);
        d[pw(2 * j + 1)] = pk(v.z, v.w);
    } else if (b < 896) {                     // g_u1th: [r][word(d)]
        int o = (b - 640) * 256 + t;          // 65536 words
        int r = o >> 9, w = o & 511;
        int wl = pw(w);
        float s = cfc_S[r];
        g_u1th[o] = pk(cfc_U[(size_t)(2 * wl) * RANK + r] * s,
                       cfc_U[(size_t)(2 * wl + 1) * RANK + r] * s);
    } else {                                  // g_u2th: [r][word(f)]
        int o = (b - 896) * 256 + t;          // 262144 words
        int r = o >> 11, w = o & 2047;
        int wl = pw(w);
        float s = cp_S[r];
        g_u2th[o] = pk(cp_U[(size_t)(2 * wl) * RANK + r] * s,
                       cp_U[(size_t)(2 * wl + 1) * RANK + r] * s);
    }
}

// ---------------- main fused kernel ----------------
__global__ void __launch_bounds__(256, 2)
fused_lowrank_mlp_kernel(const float* __restrict__ x,
                         const float* __restrict__ cfc_b,
                         const float* __restrict__ cp_b,
                         float* __restrict__ out)
{
    extern __shared__ uint32_t sm[];
    uint32_t* SA = sm + W_SA;
    uint32_t* SH = sm + W_SH;
    uint32_t* B_[2] = { sm + W_B0, sm + W_B1 };
    const uint32_t smb = (uint32_t)__cvta_generic_to_shared(sm);
    const uint32_t BA[2] = { smb + W_B0 * 4u, smb + W_B1 * 4u };

    const int tid  = threadIdx.x;
    const int lane = tid & 31;
    const int warp = tid >> 5;      // 0..7 = n-group
    const int qr   = lane >> 2;
    const int qc   = lane & 3;
    const int m0   = blockIdx.x * MT;

    // ---- staging helpers (cp.async; global layout is already permuted fp16) ----
    auto stage_u1 = [&](int ci, int b) {     // U1 chunk [128 r x 32 w]
        #pragma unroll
        for (int i = 0; i < 4; i++) {
            int u = tid + i * 256; int row = u >> 3, q = u & 7;
            cpa16(BA[b] + (BX_U1 + row * S32 + q * 4) * 4u,
                  g_u1th + (size_t)row * 512 + ci * 32 + q * 4);
        }
    };
    auto stage_2 = [&](int it, int b) {      // V1 [64 f x 64 w] + U2 [128 r x 32 w]
        #pragma unroll
        for (int i = 0; i < 4; i++) {
            int u = tid + i * 256; int row = u >> 4, q = u & 15;
            cpa16(BA[b] + (row * S64 + q * 4) * 4u,
                  g_v1h + (size_t)(it * 64 + row) * 64 + q * 4);
        }
        #pragma unroll
        for (int i = 0; i < 4; i++) {
            int u = tid + i * 256; int row = u >> 3, q = u & 7;
            cpa16(BA[b] + (BU_OFF + row * S32 + q * 4) * 4u,
                  g_u2th + (size_t)row * 2048 + it * 32 + q * 4);
        }
    };
    auto stage_3 = [&](int dc, int b) {      // V2 [64 d x 64 w]
        #pragma unroll
        for (int i = 0; i < 4; i++) {
            int u = tid + i * 256; int row = u >> 4, q = u & 15;
            cpa16(BA[b] + (row * S64 + q * 4) * 4u,
                  g_v2h + (size_t)(dc * 64 + row) * 64 + q * 4);
        }
    };

    // x chunk [32 tok x 64 d]: LDG float4 -> regs; STS packed+permuted half2
    float4 xr[2];
    auto ldx = [&](int ci) {
        if (ci < 16) {
            #pragma unroll
            for (int i = 0; i < 2; i++) {
                int idx = tid + i * 256; int row = idx >> 4, j = idx & 15;
                xr[i] = *(const float4*)(x + (size_t)(m0 + row) * DMODEL + ci * 64 + j * 4);
            }
        }
    };
    auto stx = [&](uint32_t* buf) {
        #pragma unroll
        for (int i = 0; i < 2; i++) {
            int idx = tid + i * 256; int row = idx >> 4, j = idx & 15;
            uint32_t* d = buf + row * S32;
            d[pw(2 * j)]     = pk(xr[i].x, xr[i].y);
            d[pw(2 * j + 1)] = pk(xr[i].z, xr[i].w);
        }
    };

    // ================= Phase 1: t1[32x128] = x @ (U1*S) =================
    float acc1[4][4];
    #pragma unroll
    for (int i = 0; i < 4; i++)
        #pragma unroll
        for (int j = 0; j < 4; j++) acc1[i][j] = 0.f;

    ldx(0); stx(B_[0]); stage_u1(0, 0); CPA_COMMIT();
    ldx(1); stx(B_[1]); stage_u1(1, 1); CPA_COMMIT();
    ldx(2);

    for (int ci = 0; ci < 16; ci++) {
        int b = ci & 1;
        CPA_WAIT1(); __syncthreads();
        gemm16<2, 2, S32, S32>(B_[b], B_[b] + BX_U1, warp * 16, qr, qc, acc1);
        __syncthreads();
        if (ci + 2 < 16) { stx(B_[b]); stage_u1(ci + 2, b); }
        CPA_COMMIT();
        ldx(ci + 3);
    }

    // t1 epilogue -> SA (packed half2, k-permuted)
    #pragma unroll
    for (int mi = 0; mi < 2; mi++)
        #pragma unroll
        for (int nt = 0; nt < 2; nt++) {
            int w = warp * 8 + nt * 4 + qc;      // word of cols (2w, 2w+1)
            int p = pw(w);
            int r0 = mi * 16 + qr;
            float* a = acc1[mi * 2 + nt];
            SA[r0 * S64 + p]       = pk(a[0], a[1]);
            SA[(r0 + 8) * S64 + p] = pk(a[2], a[3]);
        }

    stage_2(0, 0); CPA_COMMIT();
    stage_2(1, 1); CPA_COMMIT();

    // ===== Phase 2: 64 f-chunks of 64; t2[32x128] accumulates in registers =====
    float t2a[4][4];
    #pragma unroll
    for (int i = 0; i < 4; i++)
        #pragma unroll
        for (int j = 0; j < 4; j++) t2a[i][j] = 0.f;

    for (int it = 0; it < 64; it++) {
        int b = it & 1;
        CPA_WAIT1(); __syncthreads();

        // GEMM2: h[32x64] = t1 @ V1c^T (K=128); warp tile 32x8
        float ha[2][4];
        #pragma unroll
        for (int i = 0; i < 2; i++)
            #pragma unroll
            for (int j = 0; j < 4; j++) ha[i][j] = 0.f;
        gemm16<1, 4, S64, S64>(SA, B_[b], warp * 8, qr, qc, ha);

        // bias + exact GELU -> SH (packed half2, permuted)
        {
            int c0 = warp * 8 + 2 * qc;
            int fb = it * 64 + c0;
            float b0 = __ldg(cfc_b + fb), b1 = __ldg(cfc_b + fb + 1);
            int p = pw(warp * 4 + qc);
            #pragma unroll
            for (int mi = 0; mi < 2; mi++) {
                int r0 = mi * 16 + qr;
                float* a = ha[mi];
                SH[r0 * S32 + p]       = pk(gelu_exact(a[0] + b0), gelu_exact(a[1] + b1));
                SH[(r0 + 8) * S32 + p] = pk(gelu_exact(a[2] + b0), gelu_exact(a[3] + b1));
            }
        }
        __syncthreads();

        // GEMM3: t2[32x128] += h @ (U2*S2)c (K=64); warp tile 32x16
        gemm16<2, 2, S32, S32>(SH, B_[b] + BU_OFF, warp * 16, qr, qc, t2a);
        __syncthreads();

        if (it + 2 < 64) stage_2(it + 2, b);
        CPA_COMMIT();
    }

    // t2 epilogue -> SA (reuse)
    #pragma unroll
    for (int mi = 0; mi < 2; mi++)
        #pragma unroll
        for (int nt = 0; nt < 2; nt++) {
            int w = warp * 8 + nt * 4 + qc;
            int p = pw(w);
            int r0 = mi * 16 + qr;
            float* a = t2a[mi * 2 + nt];
            SA[r0 * S64 + p]       = pk(a[0], a[1]);
            SA[(r0 + 8) * S64 + p] = pk(a[2], a[3]);
        }

    stage_3(0, 0); CPA_COMMIT();
    stage_3(1, 1); CPA_COMMIT();

    // ================= Phase 3: out = t2 @ V2^T + b2 =================
    for (int dc = 0; dc < 16; dc++) {
        int b = dc & 1;
        CPA_WAIT1(); __syncthreads();

        float oa[2][4];
        #pragma unroll
        for (int i = 0; i < 2; i++)
            #pragma unroll
            for (int j = 0; j < 4; j++) oa[i][j] = 0.f;
        gemm16<1, 4, S64, S64>(SA, B_[b], warp * 8, qr, qc, oa);

        int db = dc * 64 + warp * 8 + 2 * qc;
        float b0 = __ldg(cp_b + db), b1 = __ldg(cp_b + db + 1);
        #pragma unroll
        for (int mi = 0; mi < 2; mi++) {
            int r0 = m0 + mi * 16 + qr;
            float* a = oa[mi];
            *(float2*)(out + (size_t)r0 * DMODEL + db) =
                make_float2(a[0] + b0, a[1] + b1);
            *(float2*)(out + (size_t)(r0 + 8) * DMODEL + db) =
                make_float2(a[2] + b0, a[3] + b1);
        }
        __syncthreads();
        if (dc + 2 < 16) stage_3(dc + 2, b);
        CPA_COMMIT();
    }
}

extern "C" void kernel_launch(void* const* d_in, const int* in_sizes, int n_in,
                              void* d_out, int out_size)
{
    const float* x     = (const float*)d_in[0];
    const float* cfc_U = (const float*)d_in[1];
    const float* cfc_S = (const float*)d_in[2];
    const float* cfc_V = (const float*)d_in[3];
    const float* cfc_b = (const float*)d_in[4];
    const float* cp_U  = (const float*)d_in[5];
    const float* cp_S  = (const float*)d_in[6];
    const float* cp_V  = (const float*)d_in[7];
    const float* cp_b  = (const float*)d_in[8];
    float* out = (float*)d_out;

    prep_w_kernel<<<1920, 256>>>(cfc_U, cfc_S, cfc_V, cp_U, cp_S, cp_V);

    const int smem_bytes = SMEM_WORDS * 4;   // 106496 -> 2 CTAs/SM
    cudaFuncSetAttribute(fused_lowrank_mlp_kernel,
                         cudaFuncAttributeMaxDynamicSharedMemorySize, smem_bytes);
    fused_lowrank_mlp_kernel<<<TOKENS / MT, 256, smem_bytes>>>(x, cfc_b, cp_b, out);
}

// round 13
// speedup vs baseline: 1.6922x; 1.0255x over previous
#include <cuda_runtime.h>
#include <cuda_fp16.h>
#include <cstdint>
#include <math.h>

#define TOKENS 8192
#define DMODEL 1024
#define DFF    4096
#define RANK   128
#define MT     64

// word strides (1 word = half2); ≡16 (mod 32) -> conflict-free LDS.128
#define S80 80       // rows of 64 data words (K=128)
#define S48 48       // rows of 32 data words (K=64)

// smem word offsets
#define W_SA 0            // t1/t2 tile: 64 x 80 = 5120
#define W_SH 5120         // h tile:     64 x 48 = 3072
#define W_B  8192         // 3 staging buffers
#define BSZ  11264        // per buffer: V1(64x80=5120) + U2(128x48=6144)
#define BU_OFF 5120       // U2 offset inside stage-2 buffer
#define BX_U1  3072       // U1 offset inside stage-1 buffer (x at 0, 64x48)
#define SMEM_WORDS (8192 + 3*BSZ)   // 41984 words = 167936 B -> 1 CTA/SM

// ---- half2-packed, k-permuted weight scratch (prep outputs) ----
__device__ uint32_t g_v1h[DFF * 64];     // cfc_V    [f][word(r)]
__device__ uint32_t g_v2h[DMODEL * 64];  // cp_V     [d][word(r)]
__device__ uint32_t g_u1th[RANK * 512];  // (U1*S)^T [r][word(d)]
__device__ uint32_t g_u2th[RANK * 2048]; // (U2*S2)^T[r][word(f)]

__device__ __forceinline__ int pw(int w) {     // permute low 4 bits (self-inverse)
    return (w & ~15) | ((w & 3) << 2) | ((w >> 2) & 3);
}
__device__ __forceinline__ uint32_t pk(float lo, float hi) {
    __half2 h = __floats2half2_rn(lo, hi);
    return *(uint32_t*)&h;
}
__device__ __forceinline__ float gelu_exact(float v) {
    return 0.5f * v * (1.f + erff(v * 0.7071067811865476f));
}
__device__ __forceinline__ void mma16(float* c,
                                      uint32_t a0, uint32_t a1, uint32_t a2, uint32_t a3,
                                      uint32_t b0, uint32_t b1) {
    asm volatile(
        "mma.sync.aligned.m16n8k16.row.col.f32.f16.f16.f32 "
        "{%0,%1,%2,%3}, {%4,%5,%6,%7}, {%8,%9}, {%0,%1,%2,%3};\n"
        : "+f"(c[0]), "+f"(c[1]), "+f"(c[2]), "+f"(c[3])
        : "r"(a0), "r"(a1), "r"(a2), "r"(a3), "r"(b0), "r"(b1));
}
__device__ __forceinline__ void cpa16(uint32_t dst, const void* src) {
    asm volatile("cp.async.cg.shared.global [%0], [%1], 16;\n" :: "r"(dst), "l"(src) : "memory");
}
#define CPA_COMMIT() asm volatile("cp.async.commit_group;\n" ::: "memory")
#define CPA_WAIT1()  asm volatile("cp.async.wait_group 1;\n" ::: "memory")
#define BAR_RG(rg)   asm volatile("bar.sync %0, 128;\n" :: "r"(1 + (rg)) : "memory")

// Warp GEMM: 32 A-rows at mrow, NT n-tiles of 8, K = KG*32.
// One LDS.128 feeds TWO m16n8k16 steps. acc[2*NT][4].
template<int NT, int KG, int SA_, int SB_>
__device__ __forceinline__ void gemm16(const uint32_t* __restrict__ A,
                                       const uint32_t* __restrict__ B,
                                       int mrow, int ncol, int qr, int qc, float (*acc)[4])
{
    #pragma unroll
    for (int kg = 0; kg < KG; kg++) {
        const int kb = kg * 16 + qc * 4;
        uint4 a0 = *(const uint4*)(A + (mrow + qr)      * SA_ + kb);
        uint4 a1 = *(const uint4*)(A + (mrow + qr + 8)  * SA_ + kb);
        uint4 a2 = *(const uint4*)(A + (mrow + qr + 16) * SA_ + kb);
        uint4 a3 = *(const uint4*)(A + (mrow + qr + 24) * SA_ + kb);
        uint4 b[NT];
        #pragma unroll
        for (int nt = 0; nt < NT; nt++)
            b[nt] = *(const uint4*)(B + (ncol + nt * 8 + qr) * SB_ + kb);
        #pragma unroll
        for (int nt = 0; nt < NT; nt++) {
            mma16(acc[nt],      a0.x, a1.x, a0.y, a1.y, b[nt].x, b[nt].y);
            mma16(acc[nt],      a0.z, a1.z, a0.w, a1.w, b[nt].z, b[nt].w);
            mma16(acc[NT + nt], a2.x, a3.x, a2.y, a3.y, b[nt].x, b[nt].y);
            mma16(acc[NT + nt], a2.z, a3.z, a2.w, a3.w, b[nt].z, b[nt].w);
        }
    }
}

// ---------------- prep: fp16-pack, fold S, transpose, k-permute (proven R11) ----------------
__global__ void prep_w_kernel(const float* __restrict__ cfc_U, const float* __restrict__ cfc_S,
                              const float* __restrict__ cfc_V,
                              const float* __restrict__ cp_U,  const float* __restrict__ cp_S,
                              const float* __restrict__ cp_V) {
    int b = blockIdx.x, t = threadIdx.x;
    if (b < 512) {
        int i = b * 256 + t;
        int row = i >> 5, j = i & 31;
        float4 v = ((const float4*)cfc_V)[i];
        uint32_t* d = g_v1h + (size_t)row * 64;
        d[pw(2 * j)]     = pk(v.x, v.y);
        d[pw(2 * j + 1)] = pk(v.z, v.w);
    } else if (b < 640) {
        int i = (b - 512) * 256 + t;
        int row = i >> 5, j = i & 31;
        float4 v = ((const float4*)cp_V)[i];
        uint32_t* d = g_v2h + (size_t)row * 64;
        d[pw(2 * j)]     = pk(v.x, v.y);
        d[pw(2 * j + 1)] = pk(v.z, v.w);
    } else if (b < 896) {
        int o = (b - 640) * 256 + t;
        int r = o >> 9, w = o & 511;
        int wl = pw(w);
        float s = cfc_S[r];
        g_u1th[o] = pk(cfc_U[(size_t)(2 * wl) * RANK + r] * s,
                       cfc_U[(size_t)(2 * wl + 1) * RANK + r] * s);
    } else {
        int o = (b - 896) * 256 + t;
        int r = o >> 11, w = o & 2047;
        int wl = pw(w);
        float s = cp_S[r];
        g_u2th[o] = pk(cp_U[(size_t)(2 * wl) * RANK + r] * s,
                       cp_U[(size_t)(2 * wl + 1) * RANK + r] * s);
    }
}

// ---------------- main fused kernel ----------------
__global__ void __launch_bounds__(256, 1)
fused_lowrank_mlp_kernel(const float* __restrict__ x,
                         const float* __restrict__ cfc_b,
                         const float* __restrict__ cp_b,
                         float* __restrict__ out)
{
    extern __shared__ uint32_t sm[];
    uint32_t* SA = sm + W_SA;
    uint32_t* SH = sm + W_SH;
    uint32_t* B_[3] = { sm + W_B, sm + W_B + BSZ, sm + W_B + 2 * BSZ };
    const uint32_t smb = (uint32_t)__cvta_generic_to_shared(sm);
    const uint32_t BA[3] = { smb + W_B * 4u, smb + (W_B + BSZ) * 4u, smb + (W_B + 2 * BSZ) * 4u };

    const int tid  = threadIdx.x;
    const int lane = tid & 31;
    const int warp = tid >> 5;
    const int qr   = lane >> 2;
    const int qc   = lane & 3;
    const int rg   = warp >> 2;         // 2 row groups of 32 rows
    const int cg   = warp & 3;          // 4 col groups
    const int mrow = rg * 32;
    const int m0   = blockIdx.x * MT;

    // ---- staging helpers ----
    auto stage_u1 = [&](int ci, int bi) {          // U1 chunk [128 r x 32 w]
        #pragma unroll
        for (int i = 0; i < 4; i++) {
            int u = tid + i * 256; int row = u >> 3, q = u & 7;
            cpa16(BA[bi] + (BX_U1 + row * S48 + q * 4) * 4u,
                  g_u1th + (size_t)row * 512 + ci * 32 + q * 4);
        }
    };
    auto stage_2 = [&](int it, int bi) {           // V1 [64 f x 64 w] + U2 [128 r x 32 w]
        #pragma unroll
        for (int i = 0; i < 4; i++) {
            int u = tid + i * 256; int row = u >> 4, q = u & 15;
            cpa16(BA[bi] + (row * S80 + q * 4) * 4u,
                  g_v1h + (size_t)(it * 64 + row) * 64 + q * 4);
        }
        #pragma unroll
        for (int i = 0; i < 4; i++) {
            int u = tid + i * 256; int row = u >> 3, q = u & 7;
            cpa16(BA[bi] + (BU_OFF + row * S48 + q * 4) * 4u,
                  g_u2th + (size_t)row * 2048 + it * 32 + q * 4);
        }
    };
    auto stage_3 = [&](int dc, int bi) {           // V2 [64 d x 64 w]
        #pragma unroll
        for (int i = 0; i < 4; i++) {
            int u = tid + i * 256; int row = u >> 4, q = u & 15;
            cpa16(BA[bi] + (row * S80 + q * 4) * 4u,
                  g_v2h + (size_t)(dc * 64 + row) * 64 + q * 4);
        }
    };

    // x chunk [64 tok x 64 d]: LDG float4 -> regs; STS packed+permuted half2
    float4 xr[4];
    auto ldx = [&](int ci) {
        if (ci < 16) {
            #pragma unroll
            for (int i = 0; i < 4; i++) {
                int idx = tid + i * 256; int row = idx >> 4, j = idx & 15;
                xr[i] = *(const float4*)(x + (size_t)(m0 + row) * DMODEL + ci * 64 + j * 4);
            }
        }
    };
    auto stx = [&](uint32_t* buf) {
        #pragma unroll
        for (int i = 0; i < 4; i++) {
            int idx = tid + i * 256; int row = idx >> 4, j = idx & 15;
            uint32_t* d = buf + row * S48;
            d[pw(2 * j)]     = pk(xr[i].x, xr[i].y);
            d[pw(2 * j + 1)] = pk(xr[i].z, xr[i].w);
        }
    };

    // ================= Phase 1: t1[64x128] = x @ (U1*S) =================
    float acc1[8][4];
    #pragma unroll
    for (int i = 0; i < 8; i++)
        #pragma unroll
        for (int j = 0; j < 4; j++) acc1[i][j] = 0.f;

    ldx(0); stx(B_[0]); stage_u1(0, 0); CPA_COMMIT();
    ldx(1); stx(B_[1]); stage_u1(1, 1); CPA_COMMIT();
    ldx(2);

    for (int ci = 0; ci < 16; ci++) {
        CPA_WAIT1(); __syncthreads();
        if (ci + 2 < 16) { stx(B_[(ci + 2) % 3]); stage_u1(ci + 2, (ci + 2) % 3); }
        CPA_COMMIT();
        ldx(ci + 3);
        const uint32_t* buf = B_[ci % 3];
        gemm16<4, 2, S48, S48>(buf, buf + BX_U1, mrow, cg * 32, qr, qc, acc1);
    }
    __syncthreads();      // all warps done phase-1 GEMMs before epilogue/staging

    // t1 epilogue -> SA (packed half2, k-permuted)
    #pragma unroll
    for (int nt = 0; nt < 4; nt++) {
        int p = pw(cg * 16 + nt * 4 + qc);
        SA[(mrow + qr) * S80 + p]      = pk(acc1[nt][0], acc1[nt][1]);
        SA[(mrow + qr + 8) * S80 + p]  = pk(acc1[nt][2], acc1[nt][3]);
        SA[(mrow + qr + 16) * S80 + p] = pk(acc1[4 + nt][0], acc1[4 + nt][1]);
        SA[(mrow + qr + 24) * S80 + p] = pk(acc1[4 + nt][2], acc1[4 + nt][3]);
    }

    stage_2(0, 0); CPA_COMMIT();
    stage_2(1, 1); CPA_COMMIT();

    // ===== Phase 2: 64 f-chunks of 64; t2[64x128] accumulates in registers
    //       ONE full sync + ONE 128-thread named barrier per iteration =====
    float t2a[8][4];
    #pragma unroll
    for (int i = 0; i < 8; i++)
        #pragma unroll
        for (int j = 0; j < 4; j++) t2a[i][j] = 0.f;

    for (int it = 0; it < 64; it++) {
        const uint32_t* buf = B_[it % 3];
        CPA_WAIT1(); __syncthreads();
        if (it + 2 < 64) stage_2(it + 2, (it + 2) % 3);   // buf (it-1)%3: freed by GEMM3(it-1)
        CPA_COMMIT();

        // GEMM2: h[64x64] = t1 @ V1c^T (K=128); warp tile 32x16
        float ha[4][4];
        #pragma unroll
        for (int i = 0; i < 4; i++)
            #pragma unroll
            for (int j = 0; j < 4; j++) ha[i][j] = 0.f;
        gemm16<2, 4, S80, S80>(SA, buf, mrow, cg * 16, qr, qc, ha);

        // bias + exact GELU -> SH (packed half2, permuted)
        #pragma unroll
        for (int nt = 0; nt < 2; nt++) {
            int c0 = cg * 16 + nt * 8 + 2 * qc;
            int fb = it * 64 + c0;
            float b0 = __ldg(cfc_b + fb), b1 = __ldg(cfc_b + fb + 1);
            int p = pw(cg * 8 + nt * 4 + qc);
            SH[(mrow + qr) * S48 + p] =
                pk(gelu_exact(ha[nt][0] + b0), gelu_exact(ha[nt][1] + b1));
            SH[(mrow + qr + 8) * S48 + p] =
                pk(gelu_exact(ha[nt][2] + b0), gelu_exact(ha[nt][3] + b1));
            SH[(mrow + qr + 16) * S48 + p] =
                pk(gelu_exact(ha[2 + nt][0] + b0), gelu_exact(ha[2 + nt][1] + b1));
            SH[(mrow + qr + 24) * S48 + p] =
                pk(gelu_exact(ha[2 + nt][2] + b0), gelu_exact(ha[2 + nt][3] + b1));
        }
        BAR_RG(rg);   // only same-row-group warps write the h rows this warp reads

        // GEMM3: t2[64x128] += h @ (U2*S2)c (K=64); warp tile 32x32
        gemm16<4, 2, S48, S48>(SH, buf + BU_OFF, mrow, cg * 32, qr, qc, t2a);
    }
    __syncthreads();      // all warps done GEMM2/GEMM3(63) before SA overwrite / buf reuse

    // t2 epilogue -> SA (reuse)
    #pragma unroll
    for (int nt = 0; nt < 4; nt++) {
        int p = pw(cg * 16 + nt * 4 + qc);
        SA[(mrow + qr) * S80 + p]      = pk(t2a[nt][0], t2a[nt][1]);
        SA[(mrow + qr + 8) * S80 + p]  = pk(t2a[nt][2], t2a[nt][3]);
        SA[(mrow + qr + 16) * S80 + p] = pk(t2a[4 + nt][0], t2a[4 + nt][1]);
        SA[(mrow + qr + 24) * S80 + p] = pk(t2a[4 + nt][2], t2a[4 + nt][3]);
    }

    stage_3(0, 0); CPA_COMMIT();
    stage_3(1, 1); CPA_COMMIT();

    // ================= Phase 3: out = t2 @ V2^T + b2 =================
    for (int dc = 0; dc < 16; dc++) {
        CPA_WAIT1(); __syncthreads();
        if (dc + 2 < 16) stage_3(dc + 2, (dc + 2) % 3);
        CPA_COMMIT();

        float oa[4][4];
        #pragma unroll
        for (int i = 0; i < 4; i++)
            #pragma unroll
            for (int j = 0; j < 4; j++) oa[i][j] = 0.f;
        gemm16<2, 4, S80, S80>(SA, B_[dc % 3], mrow, cg * 16, qr, qc, oa);

        #pragma unroll
        for (int nt = 0; nt < 2; nt++) {
            int c0 = cg * 16 + nt * 8 + 2 * qc;
            int db = dc * 64 + c0;
            float b0 = __ldg(cp_b + db), b1 = __ldg(cp_b + db + 1);
            int r0 = m0 + mrow + qr;
            *(float2*)(out + (size_t)r0 * DMODEL + db) =
                make_float2(oa[nt][0] + b0, oa[nt][1] + b1);
            *(float2*)(out + (size_t)(r0 + 8) * DMODEL + db) =
                make_float2(oa[nt][2] + b0, oa[nt][3] + b1);
            *(float2*)(out + (size_t)(r0 + 16) * DMODEL + db) =
                make_float2(oa[2 + nt][0] + b0, oa[2 + nt][1] + b1);
            *(float2*)(out + (size_t)(r0 + 24) * DMODEL + db) =
                make_float2(oa[2 + nt][2] + b0, oa[2 + nt][3] + b1);
        }
    }
}

extern "C" void kernel_launch(void* const* d_in, const int* in_sizes, int n_in,
                              void* d_out, int out_size)
{
    const float* x     = (const float*)d_in[0];
    const float* cfc_U = (const float*)d_in[1];
    const float* cfc_S = (const float*)d_in[2];
    const float* cfc_V = (const float*)d_in[3];
    const float* cfc_b = (const float*)d_in[4];
    const float* cp_U  = (const float*)d_in[5];
    const float* cp_S  = (const float*)d_in[6];
    const float* cp_V  = (const float*)d_in[7];
    const float* cp_b  = (const float*)d_in[8];
    float* out = (float*)d_out;

    prep_w_kernel<<<1920, 256>>>(cfc_U, cfc_S, cfc_V, cp_U, cp_S, cp_V);

    const int smem_bytes = SMEM_WORDS * 4;   // 167936
    cudaFuncSetAttribute(fused_lowrank_mlp_kernel,
                         cudaFuncAttributeMaxDynamicSharedMemorySize, smem_bytes);
    fused_lowrank_mlp_kernel<<<TOKENS / MT, 256, smem_bytes>>>(x, cfc_b, cp_b, out);
}